// round 12
// baseline (speedup 1.0000x reference)
#include <cuda_runtime.h>
#include <cuda_fp16.h>
#include <cstdint>

#define NH   16
#define DK   64
#define DV   64
#define NB   4
#define NL   512
#define DM   1024
#define BL   (NB*NL)   // 2048

// ---------------- scratch (device globals: allocation-free) ----------------
__device__ __half g_xh[3*BL*DM];       // fp16 copies of q,k,v inputs
__device__ __half g_wt_h[4*DM*DM];     // fp16 transposed weights [mode][n][k]
__device__ __half g_qh[NB*NH*NL*DK];   // [b,h,l,dk], pre-scaled by 1/8
__device__ __half g_kh[NB*NH*NL*DK];   // [b,h,l,dk]
__device__ __half g_vt[NB*NH*DV*NL];   // [b,h,dv,l] (transposed V)
__device__ __half g_ctx_h[BL*DM];      // [b*l, h*dv] fp16
__device__ float  g_out[BL*DM];        // pre-LN output fp32

// ---------------- helpers ----------------
__device__ __forceinline__ unsigned f22h2(float a, float b) {
    __half2 h = __floats2half2_rn(a, b);
    return *(unsigned*)&h;
}

// fp16 mma m16n8k16, f32 accumulate
__device__ __forceinline__ void mma_f16(float* d, const unsigned* a, const unsigned* b) {
    asm volatile(
        "mma.sync.aligned.m16n8k16.row.col.f32.f16.f16.f32 "
        "{%0,%1,%2,%3}, {%4,%5,%6,%7}, {%8,%9}, {%0,%1,%2,%3};\n"
        : "+f"(d[0]), "+f"(d[1]), "+f"(d[2]), "+f"(d[3])
        : "r"(a[0]), "r"(a[1]), "r"(a[2]), "r"(a[3]), "r"(b[0]), "r"(b[1]));
}

// ldmatrix x4: 4 8x8 fp16 matrices in one instruction
__device__ __forceinline__ void ldsm4(unsigned* r, unsigned saddr) {
    asm volatile(
        "ldmatrix.sync.aligned.m8n8.x4.shared.b16 {%0,%1,%2,%3}, [%4];"
        : "=r"(r[0]), "=r"(r[1]), "=r"(r[2]), "=r"(r[3]) : "r"(saddr));
}

__device__ __forceinline__ void cp16(void* dst, const void* src) {
    unsigned d = (unsigned)__cvta_generic_to_shared(dst);
    asm volatile("cp.async.cg.shared.global [%0], [%1], 16;\n" :: "r"(d), "l"(src));
}
#define CP_COMMIT() asm volatile("cp.async.commit_group;\n")
#define CP_WAIT(N)  asm volatile("cp.async.wait_group %0;\n" :: "n"(N))

__device__ __forceinline__ unsigned smem_u32(const void* p) {
    return (unsigned)__cvta_generic_to_shared(p);
}

// ---------------- prep: convert q,k,v to fp16 + transpose/convert weights ---
__global__ __launch_bounds__(256) void prep_kernel(
    const float* __restrict__ q, const float* __restrict__ k,
    const float* __restrict__ v,
    const float* __restrict__ w0, const float* __restrict__ w1,
    const float* __restrict__ w2, const float* __restrict__ w3) {
    __shared__ float t[32][33];
    int z = blockIdx.z;
    if (z < 6) {
        int tn = z >> 1;
        const float* X = (tn == 0) ? q : (tn == 1) ? k : v;
        __half* O = g_xh + (size_t)tn * BL * DM;
        int blk = blockIdx.y * 32 + blockIdx.x + (z & 1) * 1024;
        int tid = threadIdx.y * 32 + threadIdx.x;
        size_t i = (size_t)blk * 1024 + tid * 4;
        float4 f = *(const float4*)(X + i);
        uint2 o;
        o.x = f22h2(f.x, f.y);
        o.y = f22h2(f.z, f.w);
        *(uint2*)(O + i) = o;
    } else {
        int m = z - 6;
        const float* W = (m == 0) ? w0 : (m == 1) ? w1 : (m == 2) ? w2 : w3;
        __half* O = g_wt_h + (size_t)m * DM * DM;
        int bx = blockIdx.x * 32, by = blockIdx.y * 32;
        int tx = threadIdx.x, ty = threadIdx.y;
#pragma unroll
        for (int j = 0; j < 32; j += 8)
            t[ty + j][tx] = W[(size_t)(by + ty + j) * DM + bx + tx];
        __syncthreads();
#pragma unroll
        for (int j = 0; j < 32; j += 8)
            O[(size_t)(bx + ty + j) * DM + by + tx] = __float2half_rn(t[tx][ty + j]);
    }
}

// ---------------- fp16 GEMM: CTA 64x128, 8 warps (16x64), Ktile=64 ----------
//  mode 0: q proj -> g_qh (x0.125) | 1: k -> g_kh | 2: v -> g_vt (transposed)
//  mode 3: out proj + bias + residual -> g_out (fp32)
#define GWS     36                 // word (half2) stride per 64-elem row
#define GA_W    (64*GWS)           // words per A tile (64 rows)
#define GB_W    (128*GWS)          // words per B tile (128 rows)
#define GSMEM   ((2*GA_W + 2*GB_W)*4)   // bytes (55,296)

__device__ __forceinline__ void gemm_body(const __half* __restrict__ Ah,
                                          const __half* __restrict__ Bh,
                                          const float* __restrict__ bias,
                                          const float* __restrict__ resid,
                                          int mode) {
    extern __shared__ unsigned sg[];
    unsigned sb0 = smem_u32(sg);
    unsigned* Asb[2] = { sg, sg + GA_W };
    unsigned* Bsb[2] = { sg + 2*GA_W, sg + 2*GA_W + GB_W };

    int tid  = threadIdx.x;
    int warp = tid >> 5, lane = tid & 31;
    int wm = warp >> 1, wn = warp & 1;     // 4 x 2 warps over 64x128
    int m0 = blockIdx.y * 64;
    int n0 = blockIdx.x * 128;
    int g  = lane >> 2, tg = lane & 3;

    // ldmatrix per-lane byte offsets within a tile
    unsigned a_off = ((wm*16 + (lane & 15)) * GWS + (lane >> 4) * 4) * 4;
    unsigned b_off = ((wn*64 + (lane & 7) + ((lane >> 4) << 3)) * GWS
                      + ((lane >> 3) & 1) * 4) * 4;

    float acc[8][4];
#pragma unroll
    for (int j = 0; j < 8; j++)
#pragma unroll
        for (int c = 0; c < 4; c++) acc[j][c] = 0.f;

    auto load_tiles = [&](int kt, int bufi) {
        int kb = kt * 64;
#pragma unroll
        for (int i = 0; i < 2; i++) {
            int e = tid + i * 256;
            int r = e >> 3, c = e & 7;
            cp16(&Asb[bufi][r*GWS + c*4], &Ah[(size_t)(m0 + r)*DM + kb + c*8]);
        }
#pragma unroll
        for (int i = 0; i < 4; i++) {
            int e = tid + i * 256;
            int r = e >> 3, c = e & 7;
            cp16(&Bsb[bufi][r*GWS + c*4], &Bh[(size_t)(n0 + r)*DM + kb + c*8]);
        }
        CP_COMMIT();
    };

    load_tiles(0, 0);
    for (int kt = 0; kt < DM/64; kt++) {
        int cur = kt & 1;
        if (kt + 1 < DM/64) { load_tiles(kt + 1, cur ^ 1); CP_WAIT(1); }
        else                { CP_WAIT(0); }
        __syncthreads();
        unsigned uA = sb0 + cur * GA_W * 4 + a_off;
        unsigned uB = sb0 + (2*GA_W + cur * GB_W) * 4 + b_off;
#pragma unroll
        for (int ks = 0; ks < 4; ks++) {
            unsigned af[4];
            ldsm4(af, uA + ks*32);
#pragma unroll
            for (int jg = 0; jg < 4; jg++) {
                unsigned r[4];
                ldsm4(r, uB + ks*32 + jg * 16*GWS*4);
                mma_f16(acc[2*jg],     af, r);
                mma_f16(acc[2*jg + 1], af, r + 2);
            }
        }
        __syncthreads();
    }

#pragma unroll
    for (int j = 0; j < 8; j++) {
        int m  = wm * 16 + g;
        int n  = wn * 64 + j * 8 + 2 * tg;      // even; pair (n, n+1)
#pragma unroll
        for (int half_ = 0; half_ < 2; half_++) {
            int gm = m0 + m + (half_ ? 8 : 0);
            float v0 = acc[j][half_*2]     + bias[n0 + n];
            float v1 = acc[j][half_*2 + 1] + bias[n0 + n + 1];
            int gn = n0 + n;
            if (mode == 3) {
                const float* rs = resid + (size_t)gm * DM + gn;
                float* dst = g_out + (size_t)gm * DM + gn;
                dst[0] = v0 + rs[0];
                dst[1] = v1 + rs[1];
            } else {
                int b = gm >> 9, l = gm & 511, h = gn >> 6, d = gn & 63;
                if (mode == 0) {
                    unsigned* dst = (unsigned*)g_qh;
                    dst[(((size_t)(b*NH + h)*NL + l))*32 + (d >> 1)] =
                        f22h2(v0 * 0.125f, v1 * 0.125f);
                } else if (mode == 1) {
                    unsigned* dst = (unsigned*)g_kh;
                    dst[(((size_t)(b*NH + h)*NL + l))*32 + (d >> 1)] = f22h2(v0, v1);
                } else {
                    __half* vt = g_vt + ((size_t)(b*NH + h)*DV + d)*NL + l;
                    vt[0]  = __float2half_rn(v0);
                    vt[NL] = __float2half_rn(v1);
                }
            }
        }
    }
}

__global__ __launch_bounds__(256, 2) void gemm_qkv_kernel(
    const float* __restrict__ bq, const float* __restrict__ bk,
    const float* __restrict__ bv) {
    int mode = blockIdx.z;
    const float* B = (mode == 0) ? bq : (mode == 1) ? bk : bv;
    gemm_body(g_xh + (size_t)mode * BL * DM, g_wt_h + (size_t)mode * DM * DM,
              B, nullptr, mode);
}

__global__ __launch_bounds__(256, 2) void gemm_out_kernel(
    const float* __restrict__ resid, const float* __restrict__ bo) {
    gemm_body(g_ctx_h, g_wt_h + (size_t)3 * DM * DM, bo, resid, 3);
}

// ---------------- fp16 flash attention (256 thr, 8 warps x 16 q-rows) -------
#define KWS    36                  // half2-word stride for 64-wide fp16 rows
#define KT_W   (64*KWS)            // words per K or V tile

__global__ __launch_bounds__(256, 2) void attn_kernel(const float* __restrict__ bias,
                                                      const float* __restrict__ gbias) {
    extern __shared__ unsigned sm[];
    unsigned sb0 = smem_u32(sm);
    unsigned* sP = sm + 4*KT_W;             // [128][36] half2 words

    int tid = threadIdx.x, wid = tid >> 5, lane = tid & 31;
    int g = lane >> 2, tg = lane & 3;
    int qt = blockIdx.x, h = blockIdx.y, b = blockIdx.z;
    int bh = b * NH + h;
    const __half* kbase = g_kh + (size_t)bh * NL * DK;
    const __half* vbase = g_vt + (size_t)bh * DV * NL;
    int qrow0 = qt * 128 + wid * 16;
    const unsigned* qw = (const unsigned*)(g_qh + ((size_t)bh * NL + qrow0) * DK);
    const float* brow0 = bias  + ((size_t)bh * NL + qrow0 + g) * NL;
    const float* brow1 = brow0 + 8 * NL;
    const float* grow0 = gbias + ((size_t)bh * NL + qrow0 + g) * NL;
    const float* grow1 = grow0 + 8 * NL;

    // ldmatrix per-lane byte offsets
    unsigned kv_off = (((lane & 7) + ((lane >> 4) << 3)) * KWS
                       + ((lane >> 3) & 1) * 4) * 4;          // B-pattern (K,V tiles)
    unsigned p_off  = ((wid*16 + (lane & 15)) * KWS + (lane >> 4) * 4) * 4;  // A-pattern (P)
    unsigned uP = sb0 + 4*KT_W*4 + p_off;

    unsigned qf[4][4];
#pragma unroll
    for (int ks = 0; ks < 4; ks++) {
        qf[ks][0] = qw[(size_t)g * 32       + ks*8 + tg];
        qf[ks][1] = qw[(size_t)(g + 8) * 32 + ks*8 + tg];
        qf[ks][2] = qw[(size_t)g * 32       + ks*8 + tg + 4];
        qf[ks][3] = qw[(size_t)(g + 8) * 32 + ks*8 + tg + 4];
    }

    float oacc[8][4];
#pragma unroll
    for (int j = 0; j < 8; j++)
#pragma unroll
        for (int c = 0; c < 4; c++) oacc[j][c] = 0.f;
    float m0 = -1e30f, m1 = -1e30f, l0 = 0.f, l1 = 0.f;

    unsigned* sKb[2] = { sm, sm + KT_W };
    unsigned* sVb[2] = { sm + 2*KT_W, sm + 3*KT_W };
    auto load_kv = [&](int kt, int bufi) {
#pragma unroll
        for (int i = 0; i < 2; i++) {
            int e = tid + i * 256;
            int r = e >> 3, c = e & 7;
            cp16(&sKb[bufi][r*KWS + c*4], &kbase[(size_t)(kt*64 + r) * DK + c*8]);
        }
#pragma unroll
        for (int i = 0; i < 2; i++) {
            int e = tid + i * 256;
            int r = e >> 3, c = e & 7;
            cp16(&sVb[bufi][r*KWS + c*4], &vbase[(size_t)r * NL + kt*64 + c*8]);
        }
        CP_COMMIT();
    };

    load_kv(0, 0);
    for (int kt = 0; kt < 8; kt++) {
        int cur = kt & 1;
        if (kt < 7) load_kv(kt + 1, cur ^ 1);

        // bias + gbias loads issued early; consumed after QK mma
        float2 bA[8], bB[8];
#pragma unroll
        for (int j = 0; j < 8; j++) {
            int col = kt * 64 + j * 8 + 2 * tg;
            float2 b0  = *(const float2*)(brow0 + col);
            float2 gb0 = *(const float2*)(grow0 + col);
            float2 b1  = *(const float2*)(brow1 + col);
            float2 gb1 = *(const float2*)(grow1 + col);
            bA[j] = make_float2(b0.x + gb0.x, b0.y + gb0.y);
            bB[j] = make_float2(b1.x + gb1.x, b1.y + gb1.y);
        }

        float sacc[8][4];
#pragma unroll
        for (int j = 0; j < 8; j++)
#pragma unroll
            for (int c = 0; c < 4; c++) sacc[j][c] = 0.f;

        if (kt < 7) { CP_WAIT(1); }
        else        { CP_WAIT(0); }
        __syncthreads();

        unsigned uK = sb0 + cur * KT_W * 4 + kv_off;
#pragma unroll
        for (int ks = 0; ks < 4; ks++) {
#pragma unroll
            for (int jg = 0; jg < 4; jg++) {
                unsigned r[4];
                ldsm4(r, uK + ks*32 + jg * 16*KWS*4);
                mma_f16(sacc[2*jg],     qf[ks], r);
                mma_f16(sacc[2*jg + 1], qf[ks], r + 2);
            }
        }

#pragma unroll
        for (int j = 0; j < 8; j++) {
            sacc[j][0] += bA[j].x; sacc[j][1] += bA[j].y;
            sacc[j][2] += bB[j].x; sacc[j][3] += bB[j].y;
        }

        // ---- online softmax (warp-private rows; quad owns a row) ----
        float t0 = -1e30f, t1 = -1e30f;
#pragma unroll
        for (int j = 0; j < 8; j++) {
            t0 = fmaxf(t0, fmaxf(sacc[j][0], sacc[j][1]));
            t1 = fmaxf(t1, fmaxf(sacc[j][2], sacc[j][3]));
        }
        t0 = fmaxf(t0, __shfl_xor_sync(~0u, t0, 1));
        t0 = fmaxf(t0, __shfl_xor_sync(~0u, t0, 2));
        t1 = fmaxf(t1, __shfl_xor_sync(~0u, t1, 1));
        t1 = fmaxf(t1, __shfl_xor_sync(~0u, t1, 2));
        float mn0 = fmaxf(m0, t0), mn1 = fmaxf(m1, t1);
        float r0 = __expf(m0 - mn0), r1 = __expf(m1 - mn1);
        float s0 = 0.f, s1 = 0.f;
#pragma unroll
        for (int j = 0; j < 8; j++) {
            sacc[j][0] = __expf(sacc[j][0] - mn0); s0 += sacc[j][0];
            sacc[j][1] = __expf(sacc[j][1] - mn0); s0 += sacc[j][1];
            sacc[j][2] = __expf(sacc[j][2] - mn1); s1 += sacc[j][2];
            sacc[j][3] = __expf(sacc[j][3] - mn1); s1 += sacc[j][3];
        }
        s0 += __shfl_xor_sync(~0u, s0, 1); s0 += __shfl_xor_sync(~0u, s0, 2);
        s1 += __shfl_xor_sync(~0u, s1, 1); s1 += __shfl_xor_sync(~0u, s1, 2);
        l0 = l0 * r0 + s0; l1 = l1 * r1 + s1;
        m0 = mn0; m1 = mn1;
#pragma unroll
        for (int j = 0; j < 8; j++) {
            oacc[j][0] *= r0; oacc[j][1] *= r0;
            oacc[j][2] *= r1; oacc[j][3] *= r1;
        }

        // ---- P -> smem as fp16 pairs (warp-private rows), then PV mma ----
        unsigned* p0 = sP + (wid*16 + g) * KWS;
        unsigned* p1 = sP + (wid*16 + g + 8) * KWS;
#pragma unroll
        for (int j = 0; j < 8; j++) {
            p0[j*4 + tg] = f22h2(sacc[j][0], sacc[j][1]);
            p1[j*4 + tg] = f22h2(sacc[j][2], sacc[j][3]);
        }
        __syncwarp();

        unsigned uV = sb0 + (2 + cur) * KT_W * 4 + kv_off;
#pragma unroll
        for (int ks = 0; ks < 4; ks++) {
            unsigned af[4];
            ldsm4(af, uP + ks*32);
#pragma unroll
            for (int jg = 0; jg < 4; jg++) {
                unsigned r[4];
                ldsm4(r, uV + ks*32 + jg * 16*KWS*4);
                mma_f16(oacc[2*jg],     af, r);
                mma_f16(oacc[2*jg + 1], af, r + 2);
            }
        }
        __syncthreads();
    }

    float inv0 = 1.f / l0, inv1 = 1.f / l1;
    size_t gr0 = (size_t)b * NL + qt * 128 + wid * 16 + g;
    unsigned* out0 = (unsigned*)g_ctx_h + gr0 * 512 + h * 32;
    unsigned* out1 = out0 + (size_t)8 * 512;
#pragma unroll
    for (int j = 0; j < 8; j++) {
        out0[j*4 + tg] = f22h2(oacc[j][0] * inv0, oacc[j][1] * inv0);
        out1[j*4 + tg] = f22h2(oacc[j][2] * inv1, oacc[j][3] * inv1);
    }
}

// ---------------- LayerNorm ----------------
__global__ __launch_bounds__(256) void ln_kernel(const float* __restrict__ gamma,
                                                 const float* __restrict__ beta,
                                                 float* __restrict__ out) {
    __shared__ float red[16];
    int row = blockIdx.x, tid = threadIdx.x;
    const float* x = g_out + (size_t)row * DM;
    float v[4];
    float s = 0.f, s2 = 0.f;
#pragma unroll
    for (int i = 0; i < 4; i++) {
        v[i] = x[tid + i * 256];
        s += v[i]; s2 += v[i] * v[i];
    }
#pragma unroll
    for (int o = 16; o; o >>= 1) {
        s  += __shfl_xor_sync(~0u, s, o);
        s2 += __shfl_xor_sync(~0u, s2, o);
    }
    int warp = tid >> 5, lane = tid & 31;
    if (lane == 0) { red[warp] = s; red[warp + 8] = s2; }
    __syncthreads();
    float ts = 0.f, ts2 = 0.f;
#pragma unroll
    for (int i = 0; i < 8; i++) { ts += red[i]; ts2 += red[i + 8]; }
    float mean = ts * (1.f / DM);
    float var  = ts2 * (1.f / DM) - mean * mean;
    float inv  = rsqrtf(var + 1e-6f);
#pragma unroll
    for (int i = 0; i < 4; i++) {
        int d = tid + i * 256;
        out[(size_t)row * DM + d] = (v[i] - mean) * inv * gamma[d] + beta[d];
    }
}

// ---------------- launch ----------------
extern "C" void kernel_launch(void* const* d_in, const int* in_sizes, int n_in,
                              void* d_out, int out_size) {
    const float* q     = (const float*)d_in[0];
    const float* k     = (const float*)d_in[1];
    const float* v     = (const float*)d_in[2];
    const float* bias  = (const float*)d_in[3];
    const float* gbias = (const float*)d_in[4];
    const float* wq    = (const float*)d_in[5];
    const float* bq    = (const float*)d_in[6];
    const float* wk    = (const float*)d_in[7];
    const float* bk    = (const float*)d_in[8];
    const float* wv    = (const float*)d_in[9];
    const float* bv    = (const float*)d_in[10];
    const float* wo    = (const float*)d_in[11];
    const float* bo    = (const float*)d_in[12];
    const float* ln_g  = (const float*)d_in[13];
    const float* ln_b  = (const float*)d_in[14];
    float* out = (float*)d_out;

    const int gemm_smem = GSMEM;                               // 55,296 B
    const int attn_smem = (4*KT_W + 128*KWS) * 4;              // 55,296 B
    cudaFuncSetAttribute((const void*)gemm_qkv_kernel,
                         cudaFuncAttributeMaxDynamicSharedMemorySize, gemm_smem);
    cudaFuncSetAttribute((const void*)gemm_out_kernel,
                         cudaFuncAttributeMaxDynamicSharedMemorySize, gemm_smem);
    cudaFuncSetAttribute((const void*)attn_kernel,
                         cudaFuncAttributeMaxDynamicSharedMemorySize, attn_smem);

    prep_kernel<<<dim3(32, 32, 10), dim3(32, 8)>>>(q, k, v, wq, wk, wv, wo);
    gemm_qkv_kernel<<<dim3(8, 32, 3), 256, gemm_smem>>>(bq, bk, bv);
    attn_kernel<<<dim3(4, NH, NB), 256, attn_smem>>>(bias, gbias);
    gemm_out_kernel<<<dim3(8, 32), 256, gemm_smem>>>(q, bo);
    ln_kernel<<<BL, 256>>>(ln_g, ln_b, out);
}

// round 17
// speedup vs baseline: 1.1639x; 1.1639x over previous
#include <cuda_runtime.h>
#include <cuda_fp16.h>
#include <cstdint>

#define NH   16
#define DK   64
#define DV   64
#define NB   4
#define NL   512
#define DM   1024
#define BL   (NB*NL)   // 2048

// ---------------- scratch (device globals: allocation-free) ----------------
__device__ __half g_xh[3*BL*DM];       // fp16 copies of q,k,v inputs
__device__ __half g_wt_h[4*DM*DM];     // fp16 transposed weights [mode][n][k]
__device__ __half g_qh[NB*NH*NL*DK];   // [b,h,l,dk], pre-scaled by 1/8
__device__ __half g_kh[NB*NH*NL*DK];   // [b,h,l,dk]
__device__ __half g_vt[NB*NH*DV*NL];   // [b,h,dv,l] (transposed V)
__device__ __half g_ctx_h[BL*DM];      // [b*l, h*dv] fp16
__device__ float  g_out[BL*DM];        // pre-LN output fp32

// ---------------- helpers ----------------
__device__ __forceinline__ unsigned f22h2(float a, float b) {
    __half2 h = __floats2half2_rn(a, b);
    return *(unsigned*)&h;
}

// fp16 mma m16n8k16, f32 accumulate
__device__ __forceinline__ void mma_f16(float* d, const unsigned* a, const unsigned* b) {
    asm volatile(
        "mma.sync.aligned.m16n8k16.row.col.f32.f16.f16.f32 "
        "{%0,%1,%2,%3}, {%4,%5,%6,%7}, {%8,%9}, {%0,%1,%2,%3};\n"
        : "+f"(d[0]), "+f"(d[1]), "+f"(d[2]), "+f"(d[3])
        : "r"(a[0]), "r"(a[1]), "r"(a[2]), "r"(a[3]), "r"(b[0]), "r"(b[1]));
}

// ldmatrix x4: 4 8x8 fp16 matrices in one instruction
__device__ __forceinline__ void ldsm4(unsigned* r, unsigned saddr) {
    asm volatile(
        "ldmatrix.sync.aligned.m8n8.x4.shared.b16 {%0,%1,%2,%3}, [%4];"
        : "=r"(r[0]), "=r"(r[1]), "=r"(r[2]), "=r"(r[3]) : "r"(saddr));
}

__device__ __forceinline__ void cp16(void* dst, const void* src) {
    unsigned d = (unsigned)__cvta_generic_to_shared(dst);
    asm volatile("cp.async.cg.shared.global [%0], [%1], 16;\n" :: "r"(d), "l"(src));
}
#define CP_COMMIT() asm volatile("cp.async.commit_group;\n")
#define CP_WAIT(N)  asm volatile("cp.async.wait_group %0;\n" :: "n"(N))

__device__ __forceinline__ unsigned smem_u32(const void* p) {
    return (unsigned)__cvta_generic_to_shared(p);
}

// ---------------- prep: convert q,k,v to fp16 + transpose/convert weights ---
__global__ __launch_bounds__(256) void prep_kernel(
    const float* __restrict__ q, const float* __restrict__ k,
    const float* __restrict__ v,
    const float* __restrict__ w0, const float* __restrict__ w1,
    const float* __restrict__ w2, const float* __restrict__ w3) {
    __shared__ float t[32][33];
    int z = blockIdx.z;
    if (z < 6) {
        int tn = z >> 1;
        const float* X = (tn == 0) ? q : (tn == 1) ? k : v;
        __half* O = g_xh + (size_t)tn * BL * DM;
        int blk = blockIdx.y * 32 + blockIdx.x + (z & 1) * 1024;
        int tid = threadIdx.y * 32 + threadIdx.x;
        size_t i = (size_t)blk * 1024 + tid * 4;
        float4 f = *(const float4*)(X + i);
        uint2 o;
        o.x = f22h2(f.x, f.y);
        o.y = f22h2(f.z, f.w);
        *(uint2*)(O + i) = o;
    } else {
        int m = z - 6;
        const float* W = (m == 0) ? w0 : (m == 1) ? w1 : (m == 2) ? w2 : w3;
        __half* O = g_wt_h + (size_t)m * DM * DM;
        int bx = blockIdx.x * 32, by = blockIdx.y * 32;
        int tx = threadIdx.x, ty = threadIdx.y;
#pragma unroll
        for (int j = 0; j < 32; j += 8)
            t[ty + j][tx] = W[(size_t)(by + ty + j) * DM + bx + tx];
        __syncthreads();
#pragma unroll
        for (int j = 0; j < 32; j += 8)
            O[(size_t)(bx + ty + j) * DM + by + tx] = __float2half_rn(t[tx][ty + j]);
    }
}

// ---------------- fp16 GEMM: CTA 128x128, 8 warps (32x64), Ktile=64 ---------
//  mode 0: q proj -> g_qh (x0.125) | 1: k -> g_kh | 2: v -> g_vt (transposed)
//  mode 3: out proj + bias + residual -> g_out (fp32)
#define GWS     36                 // word (half2) stride per 64-elem row
#define GT_W    (128*GWS)          // words per tile
#define GSMEM   (4*GT_W*4)         // 2 A + 2 B buffers, bytes (73,728)

__device__ __forceinline__ void gemm_body(const __half* __restrict__ Ah,
                                          const __half* __restrict__ Bh,
                                          const float* __restrict__ bias,
                                          const float* __restrict__ resid,
                                          int mode) {
    extern __shared__ unsigned sg[];
    unsigned sb0 = smem_u32(sg);
    unsigned* Asb[2] = { sg, sg + GT_W };
    unsigned* Bsb[2] = { sg + 2*GT_W, sg + 3*GT_W };

    int tid  = threadIdx.x;
    int warp = tid >> 5, lane = tid & 31;
    int wm = warp >> 1, wn = warp & 1;     // 4 x 2 warps over 128x128
    int m0 = blockIdx.y * 128;
    int n0 = blockIdx.x * 128;
    int g  = lane >> 2, tg = lane & 3;

    // ldmatrix per-lane byte offsets within a tile
    unsigned a_off = ((wm*32 + (lane & 15)) * GWS + (lane >> 4) * 4) * 4;
    unsigned b_off = ((wn*64 + (lane & 7) + ((lane >> 4) << 3)) * GWS
                      + ((lane >> 3) & 1) * 4) * 4;

    float acc[2][8][4];
#pragma unroll
    for (int i = 0; i < 2; i++)
#pragma unroll
        for (int j = 0; j < 8; j++)
#pragma unroll
            for (int c = 0; c < 4; c++) acc[i][j][c] = 0.f;

    auto load_tiles = [&](int kt, int bufi) {
        int kb = kt * 64;
#pragma unroll
        for (int i = 0; i < 4; i++) {
            int e = tid + i * 256;
            int r = e >> 3, c = e & 7;
            cp16(&Asb[bufi][r*GWS + c*4], &Ah[(size_t)(m0 + r)*DM + kb + c*8]);
        }
#pragma unroll
        for (int i = 0; i < 4; i++) {
            int e = tid + i * 256;
            int r = e >> 3, c = e & 7;
            cp16(&Bsb[bufi][r*GWS + c*4], &Bh[(size_t)(n0 + r)*DM + kb + c*8]);
        }
        CP_COMMIT();
    };

    load_tiles(0, 0);
    for (int kt = 0; kt < DM/64; kt++) {
        int cur = kt & 1;
        if (kt + 1 < DM/64) { load_tiles(kt + 1, cur ^ 1); CP_WAIT(1); }
        else                { CP_WAIT(0); }
        __syncthreads();
        unsigned uA = sb0 + cur * GT_W * 4 + a_off;
        unsigned uB = sb0 + (2 + cur) * GT_W * 4 + b_off;
#pragma unroll
        for (int ks = 0; ks < 4; ks++) {
            unsigned af0[4], af1[4];
            ldsm4(af0, uA + ks*32);
            ldsm4(af1, uA + ks*32 + 16*GWS*4);
#pragma unroll
            for (int jg = 0; jg < 4; jg++) {
                unsigned r[4];
                ldsm4(r, uB + ks*32 + jg * 16*GWS*4);
                mma_f16(acc[0][2*jg],     af0, r);
                mma_f16(acc[0][2*jg + 1], af0, r + 2);
                mma_f16(acc[1][2*jg],     af1, r);
                mma_f16(acc[1][2*jg + 1], af1, r + 2);
            }
        }
        __syncthreads();
    }

#pragma unroll
    for (int i = 0; i < 2; i++) {
#pragma unroll
        for (int j = 0; j < 8; j++) {
            int m  = wm * 32 + i * 16 + g;
            int n  = wn * 64 + j * 8 + 2 * tg;      // even; pair (n, n+1)
#pragma unroll
            for (int half_ = 0; half_ < 2; half_++) {
                int gm = m0 + m + (half_ ? 8 : 0);
                float v0 = acc[i][j][half_*2]     + bias[n0 + n];
                float v1 = acc[i][j][half_*2 + 1] + bias[n0 + n + 1];
                int gn = n0 + n;
                if (mode == 3) {
                    const float* rs = resid + (size_t)gm * DM + gn;
                    float* dst = g_out + (size_t)gm * DM + gn;
                    dst[0] = v0 + rs[0];
                    dst[1] = v1 + rs[1];
                } else {
                    int b = gm >> 9, l = gm & 511, h = gn >> 6, d = gn & 63;
                    if (mode == 0) {
                        unsigned* dst = (unsigned*)g_qh;
                        dst[(((size_t)(b*NH + h)*NL + l))*32 + (d >> 1)] =
                            f22h2(v0 * 0.125f, v1 * 0.125f);
                    } else if (mode == 1) {
                        unsigned* dst = (unsigned*)g_kh;
                        dst[(((size_t)(b*NH + h)*NL + l))*32 + (d >> 1)] = f22h2(v0, v1);
                    } else {
                        __half* vt = g_vt + ((size_t)(b*NH + h)*DV + d)*NL + l;
                        vt[0]  = __float2half_rn(v0);
                        vt[NL] = __float2half_rn(v1);
                    }
                }
            }
        }
    }
}

__global__ __launch_bounds__(256, 2) void gemm_qkv_kernel(
    const float* __restrict__ bq, const float* __restrict__ bk,
    const float* __restrict__ bv) {
    int mode = blockIdx.z;
    const float* B = (mode == 0) ? bq : (mode == 1) ? bk : bv;
    gemm_body(g_xh + (size_t)mode * BL * DM, g_wt_h + (size_t)mode * DM * DM,
              B, nullptr, mode);
}

__global__ __launch_bounds__(256, 2) void gemm_out_kernel(
    const float* __restrict__ resid, const float* __restrict__ bo) {
    gemm_body(g_ctx_h, g_wt_h + (size_t)3 * DM * DM, bo, resid, 3);
}

// ---------------- fp16 flash attention (256 thr, 8 warps x 16 q-rows) -------
// bias loads pipelined one full iteration ahead (issued before PV of kt-1)
#define KWS    36                  // half2-word stride for 64-wide fp16 rows
#define KT_W   (64*KWS)            // words per K or V tile

__global__ __launch_bounds__(256, 2) void attn_kernel(const float* __restrict__ bias,
                                                      const float* __restrict__ gbias) {
    extern __shared__ unsigned sm[];
    unsigned sb0 = smem_u32(sm);
    unsigned* sP = sm + 4*KT_W;             // [128][36] half2 words

    int tid = threadIdx.x, wid = tid >> 5, lane = tid & 31;
    int g = lane >> 2, tg = lane & 3;
    int qt = blockIdx.x, h = blockIdx.y, b = blockIdx.z;
    int bh = b * NH + h;
    const __half* kbase = g_kh + (size_t)bh * NL * DK;
    const __half* vbase = g_vt + (size_t)bh * DV * NL;
    int qrow0 = qt * 128 + wid * 16;
    const unsigned* qw = (const unsigned*)(g_qh + ((size_t)bh * NL + qrow0) * DK);
    const float* brow0 = bias  + ((size_t)bh * NL + qrow0 + g) * NL;
    const float* brow1 = brow0 + 8 * NL;
    const float* grow0 = gbias + ((size_t)bh * NL + qrow0 + g) * NL;
    const float* grow1 = grow0 + 8 * NL;

    // ldmatrix per-lane byte offsets
    unsigned kv_off = (((lane & 7) + ((lane >> 4) << 3)) * KWS
                       + ((lane >> 3) & 1) * 4) * 4;          // B-pattern (K,V tiles)
    unsigned p_off  = ((wid*16 + (lane & 15)) * KWS + (lane >> 4) * 4) * 4;  // A-pattern (P)
    unsigned uP = sb0 + 4*KT_W*4 + p_off;

    unsigned qf[4][4];
#pragma unroll
    for (int ks = 0; ks < 4; ks++) {
        qf[ks][0] = qw[(size_t)g * 32       + ks*8 + tg];
        qf[ks][1] = qw[(size_t)(g + 8) * 32 + ks*8 + tg];
        qf[ks][2] = qw[(size_t)g * 32       + ks*8 + tg + 4];
        qf[ks][3] = qw[(size_t)(g + 8) * 32 + ks*8 + tg + 4];
    }

    float oacc[8][4];
#pragma unroll
    for (int j = 0; j < 8; j++)
#pragma unroll
        for (int c = 0; c < 4; c++) oacc[j][c] = 0.f;
    float m0 = -1e30f, m1 = -1e30f, l0 = 0.f, l1 = 0.f;

    unsigned* sKb[2] = { sm, sm + KT_W };
    unsigned* sVb[2] = { sm + 2*KT_W, sm + 3*KT_W };
    auto load_kv = [&](int kt, int bufi) {
#pragma unroll
        for (int i = 0; i < 2; i++) {
            int e = tid + i * 256;
            int r = e >> 3, c = e & 7;
            cp16(&sKb[bufi][r*KWS + c*4], &kbase[(size_t)(kt*64 + r) * DK + c*8]);
        }
#pragma unroll
        for (int i = 0; i < 2; i++) {
            int e = tid + i * 256;
            int r = e >> 3, c = e & 7;
            cp16(&sVb[bufi][r*KWS + c*4], &vbase[(size_t)r * NL + kt*64 + c*8]);
        }
        CP_COMMIT();
    };

    // bias + gbias register prefetch (loads for iteration kt issued during
    // the PV phase of iteration kt-1 → use-to-issue distance covers DRAM lat)
    float2 bA[8], bB[8];
    auto load_bias = [&](int kt) {
#pragma unroll
        for (int j = 0; j < 8; j++) {
            int col = kt * 64 + j * 8 + 2 * tg;
            float2 b0  = *(const float2*)(brow0 + col);
            float2 gb0 = *(const float2*)(grow0 + col);
            float2 b1  = *(const float2*)(brow1 + col);
            float2 gb1 = *(const float2*)(grow1 + col);
            bA[j] = make_float2(b0.x + gb0.x, b0.y + gb0.y);
            bB[j] = make_float2(b1.x + gb1.x, b1.y + gb1.y);
        }
    };

    load_bias(0);
    load_kv(0, 0);
    for (int kt = 0; kt < 8; kt++) {
        int cur = kt & 1;
        if (kt < 7) load_kv(kt + 1, cur ^ 1);

        float sacc[8][4];
#pragma unroll
        for (int j = 0; j < 8; j++)
#pragma unroll
            for (int c = 0; c < 4; c++) sacc[j][c] = 0.f;

        if (kt < 7) { CP_WAIT(1); }
        else        { CP_WAIT(0); }
        __syncthreads();

        unsigned uK = sb0 + cur * KT_W * 4 + kv_off;
#pragma unroll
        for (int ks = 0; ks < 4; ks++) {
#pragma unroll
            for (int jg = 0; jg < 4; jg++) {
                unsigned r[4];
                ldsm4(r, uK + ks*32 + jg * 16*KWS*4);
                mma_f16(sacc[2*jg],     qf[ks], r);
                mma_f16(sacc[2*jg + 1], qf[ks], r + 2);
            }
        }

        // add prefetched biases (loaded one iteration ago)
#pragma unroll
        for (int j = 0; j < 8; j++) {
            sacc[j][0] += bA[j].x; sacc[j][1] += bA[j].y;
            sacc[j][2] += bB[j].x; sacc[j][3] += bB[j].y;
        }

        // ---- online softmax (warp-private rows; quad owns a row) ----
        float t0 = -1e30f, t1 = -1e30f;
#pragma unroll
        for (int j = 0; j < 8; j++) {
            t0 = fmaxf(t0, fmaxf(sacc[j][0], sacc[j][1]));
            t1 = fmaxf(t1, fmaxf(sacc[j][2], sacc[j][3]));
        }
        t0 = fmaxf(t0, __shfl_xor_sync(~0u, t0, 1));
        t0 = fmaxf(t0, __shfl_xor_sync(~0u, t0, 2));
        t1 = fmaxf(t1, __shfl_xor_sync(~0u, t1, 1));
        t1 = fmaxf(t1, __shfl_xor_sync(~0u, t1, 2));
        float mn0 = fmaxf(m0, t0), mn1 = fmaxf(m1, t1);
        float r0 = __expf(m0 - mn0), r1 = __expf(m1 - mn1);
        float s0 = 0.f, s1 = 0.f;
#pragma unroll
        for (int j = 0; j < 8; j++) {
            sacc[j][0] = __expf(sacc[j][0] - mn0); s0 += sacc[j][0];
            sacc[j][1] = __expf(sacc[j][1] - mn0); s0 += sacc[j][1];
            sacc[j][2] = __expf(sacc[j][2] - mn1); s1 += sacc[j][2];
            sacc[j][3] = __expf(sacc[j][3] - mn1); s1 += sacc[j][3];
        }
        s0 += __shfl_xor_sync(~0u, s0, 1); s0 += __shfl_xor_sync(~0u, s0, 2);
        s1 += __shfl_xor_sync(~0u, s1, 1); s1 += __shfl_xor_sync(~0u, s1, 2);
        l0 = l0 * r0 + s0; l1 = l1 * r1 + s1;
        m0 = mn0; m1 = mn1;
#pragma unroll
        for (int j = 0; j < 8; j++) {
            oacc[j][0] *= r0; oacc[j][1] *= r0;
            oacc[j][2] *= r1; oacc[j][3] *= r1;
        }

        // ---- P -> smem as fp16 pairs (warp-private rows) ----
        unsigned* p0 = sP + (wid*16 + g) * KWS;
        unsigned* p1 = sP + (wid*16 + g + 8) * KWS;
#pragma unroll
        for (int j = 0; j < 8; j++) {
            p0[j*4 + tg] = f22h2(sacc[j][0], sacc[j][1]);
            p1[j*4 + tg] = f22h2(sacc[j][2], sacc[j][3]);
        }
        __syncwarp();

        // issue NEXT iteration's bias loads here — they overlap PV + barrier
        // + next KV wait + next QK mma before being consumed
        if (kt < 7) load_bias(kt + 1);

        unsigned uV = sb0 + (2 + cur) * KT_W * 4 + kv_off;
#pragma unroll
        for (int ks = 0; ks < 4; ks++) {
            unsigned af[4];
            ldsm4(af, uP + ks*32);
#pragma unroll
            for (int jg = 0; jg < 4; jg++) {
                unsigned r[4];
                ldsm4(r, uV + ks*32 + jg * 16*KWS*4);
                mma_f16(oacc[2*jg],     af, r);
                mma_f16(oacc[2*jg + 1], af, r + 2);
            }
        }
        __syncthreads();
    }

    float inv0 = 1.f / l0, inv1 = 1.f / l1;
    size_t gr0 = (size_t)b * NL + qt * 128 + wid * 16 + g;
    unsigned* out0 = (unsigned*)g_ctx_h + gr0 * 512 + h * 32;
    unsigned* out1 = out0 + (size_t)8 * 512;
#pragma unroll
    for (int j = 0; j < 8; j++) {
        out0[j*4 + tg] = f22h2(oacc[j][0] * inv0, oacc[j][1] * inv0);
        out1[j*4 + tg] = f22h2(oacc[j][2] * inv1, oacc[j][3] * inv1);
    }
}

// ---------------- LayerNorm ----------------
__global__ __launch_bounds__(256) void ln_kernel(const float* __restrict__ gamma,
                                                 const float* __restrict__ beta,
                                                 float* __restrict__ out) {
    __shared__ float red[16];
    int row = blockIdx.x, tid = threadIdx.x;
    const float* x = g_out + (size_t)row * DM;
    float v[4];
    float s = 0.f, s2 = 0.f;
#pragma unroll
    for (int i = 0; i < 4; i++) {
        v[i] = x[tid + i * 256];
        s += v[i]; s2 += v[i] * v[i];
    }
#pragma unroll
    for (int o = 16; o; o >>= 1) {
        s  += __shfl_xor_sync(~0u, s, o);
        s2 += __shfl_xor_sync(~0u, s2, o);
    }
    int warp = tid >> 5, lane = tid & 31;
    if (lane == 0) { red[warp] = s; red[warp + 8] = s2; }
    __syncthreads();
    float ts = 0.f, ts2 = 0.f;
#pragma unroll
    for (int i = 0; i < 8; i++) { ts += red[i]; ts2 += red[i + 8]; }
    float mean = ts * (1.f / DM);
    float var  = ts2 * (1.f / DM) - mean * mean;
    float inv  = rsqrtf(var + 1e-6f);
#pragma unroll
    for (int i = 0; i < 4; i++) {
        int d = tid + i * 256;
        out[(size_t)row * DM + d] = (v[i] - mean) * inv * gamma[d] + beta[d];
    }
}

// ---------------- launch ----------------
extern "C" void kernel_launch(void* const* d_in, const int* in_sizes, int n_in,
                              void* d_out, int out_size) {
    const float* q     = (const float*)d_in[0];
    const float* k     = (const float*)d_in[1];
    const float* v     = (const float*)d_in[2];
    const float* bias  = (const float*)d_in[3];
    const float* gbias = (const float*)d_in[4];
    const float* wq    = (const float*)d_in[5];
    const float* bq    = (const float*)d_in[6];
    const float* wk    = (const float*)d_in[7];
    const float* bk    = (const float*)d_in[8];
    const float* wv    = (const float*)d_in[9];
    const float* bv    = (const float*)d_in[10];
    const float* wo    = (const float*)d_in[11];
    const float* bo    = (const float*)d_in[12];
    const float* ln_g  = (const float*)d_in[13];
    const float* ln_b  = (const float*)d_in[14];
    float* out = (float*)d_out;

    const int gemm_smem = GSMEM;                               // 73,728 B
    const int attn_smem = (4*KT_W + 128*KWS) * 4;              // 55,296 B
    cudaFuncSetAttribute((const void*)gemm_qkv_kernel,
                         cudaFuncAttributeMaxDynamicSharedMemorySize, gemm_smem);
    cudaFuncSetAttribute((const void*)gemm_out_kernel,
                         cudaFuncAttributeMaxDynamicSharedMemorySize, gemm_smem);
    cudaFuncSetAttribute((const void*)attn_kernel,
                         cudaFuncAttributeMaxDynamicSharedMemorySize, attn_smem);

    prep_kernel<<<dim3(32, 32, 10), dim3(32, 8)>>>(q, k, v, wq, wk, wv, wo);
    gemm_qkv_kernel<<<dim3(8, 16, 3), 256, gemm_smem>>>(bq, bk, bv);
    attn_kernel<<<dim3(4, NH, NB), 256, attn_smem>>>(bias, gbias);
    gemm_out_kernel<<<dim3(8, 16), 256, gemm_smem>>>(q, bo);
    ln_kernel<<<BL, 256>>>(ln_g, ln_b, out);
}